// round 9
// baseline (speedup 1.0000x reference)
#include <cuda_runtime.h>
#include <stdint.h>

#define N_NODES 100000
#define E_EDGES 1600000
#define HID 64
#define CAP 128            // max in-degree slots per node (Poisson(16): overflow ~impossible)
#define CAPSHIFT 7

// ---------------- scratch (no allocation allowed) ----------------
__device__ float g_bufA[N_NODES * HID];        // h_lin (GEMM out)
__device__ float g_bufB[N_NODES * HID];        // layer output h
__device__ int   g_cnt[N_NODES];               // per-dst in-degree (excl self loop)
__device__ uint2 g_csr[(size_t)N_NODES * CAP]; // {src, norm_bits} bucketed by dst
__device__ int   g_is64;                       // 1 if edge_index is int64

__device__ __forceinline__ float lrelu1(float v) {
    return fmaxf(v, 0.f) + 0.01f * fminf(v, 0.f);
}

// ---------------- dtype detect (block 0) + zero cnt (blocks 1..) ----------
__global__ void k_detect_zero(const unsigned int* __restrict__ u32buf,
                              int* __restrict__ cnt, int n) {
    if (blockIdx.x == 0) {
        __shared__ unsigned int s_or[256];
        unsigned int acc = 0;
        for (int i = threadIdx.x; i < 2048; i += 256)
            acc |= u32buf[2 * i + 1];          // hi word of candidate int64 #i
        s_or[threadIdx.x] = acc;
        __syncthreads();
        for (int s = 128; s > 0; s >>= 1) {
            if (threadIdx.x < s) s_or[threadIdx.x] |= s_or[threadIdx.x + s];
            __syncthreads();
        }
        if (threadIdx.x == 0) g_is64 = (s_or[0] == 0) ? 1 : 0;
    } else {
        int i = (blockIdx.x - 1) * blockDim.x + threadIdx.x;
        if (i < n) cnt[i] = 0;
    }
}

__device__ __forceinline__ int load_idx(const unsigned int* u32buf, long long elem, int is64, int n) {
    unsigned int v = is64 ? u32buf[2 * elem] : u32buf[elem];
    int iv = (int)v;
    return min(max(iv, 0), n - 1);
}

// ---------------- bucket fill: single pass over edge list ----------------
__global__ void k_fill(const unsigned int* __restrict__ ei, int* __restrict__ cnt,
                       uint2* __restrict__ csr, int E, int n) {
    int e = blockIdx.x * blockDim.x + threadIdx.x;
    if (e < E) {
        int is64 = g_is64;
        int s = load_idx(ei, e, is64, n);
        int d = load_idx(ei, (long long)E + e, is64, n);
        int pos = atomicAdd(cnt + d, 1);
        if (pos < CAP)
            csr[((size_t)d << CAPSHIFT) + pos] = make_uint2((unsigned int)s, 0u);
    }
}

// ---------------- norm pass: csr[.].y = rsqrt(1+cnt[s]) * rsqrt(1+cnt[d]) --
// One warp per destination node.
__global__ __launch_bounds__(256)
void k_norm(const int* __restrict__ cnt, uint2* __restrict__ csr, int n) {
    int warp = (blockIdx.x * blockDim.x + threadIdx.x) >> 5;
    int lane = threadIdx.x & 31;
    if (warp >= n) return;
    int node = warp;

    int m = min(__ldg(cnt + node), CAP);
    float dd = rsqrtf(1.0f + (float)__ldg(cnt + node));
    size_t base = (size_t)node << CAPSHIFT;

    for (int i = lane; i < m; i += 32) {
        uint2 e = csr[base + i];
        int cs = __ldg(cnt + e.x);
        float w = rsqrtf(1.0f + (float)cs) * dd;
        csr[base + i] = make_uint2(e.x, __float_as_uint(w));
    }
}

// ---------------- GEMM: out[n,64] = in[n,64] @ W[64,64] (scalar FFMA) ------
__global__ __launch_bounds__(128)
void k_gemm64(const float* __restrict__ in, const float* __restrict__ W,
              float* __restrict__ out, int n) {
    __shared__ float Ws[64 * 64];
    for (int i = threadIdx.x; i < 64 * 16; i += blockDim.x)
        ((float4*)Ws)[i] = ((const float4*)W)[i];
    __syncthreads();

    int row = blockIdx.x * blockDim.x + threadIdx.x;
    if (row >= n) return;

    float acc[64];
#pragma unroll
    for (int j = 0; j < 64; j++) acc[j] = 0.f;

    const float4* inr = (const float4*)(in + (size_t)row * HID);

#pragma unroll 4
    for (int k4 = 0; k4 < 16; k4++) {
        float4 v = inr[k4];
        float av[4] = {v.x, v.y, v.z, v.w};
#pragma unroll
        for (int kk = 0; kk < 4; kk++) {
            const float* wrow = Ws + (k4 * 4 + kk) * 64;
#pragma unroll
            for (int j = 0; j < 64; j++)
                acc[j] = fmaf(av[kk], wrow[j], acc[j]);
        }
    }

    float4* outr = (float4*)(out + (size_t)row * HID);
#pragma unroll
    for (int j = 0; j < 16; j++)
        outr[j] = make_float4(acc[4 * j], acc[4 * j + 1], acc[4 * j + 2], acc[4 * j + 3]);
}

// ---------------- gather: h[node] = lrelu(bias + dinv^2*lin[node]
//                                 + sum_e norm_e * lin[src_e]) ----------------
// One warp per destination node; lane owns 2 feature columns (float2).
// (R8 unroll-2 body; offsets now from fixed-capacity buckets)
__global__ __launch_bounds__(256)
void k_gather(const float* __restrict__ lin, const uint2* __restrict__ csr,
              const int* __restrict__ cnt,
              const float* __restrict__ bias, float* __restrict__ outp, int n) {
    int warp = (blockIdx.x * blockDim.x + threadIdx.x) >> 5;
    int lane = threadIdx.x & 31;
    if (warp >= n) return;
    int node = warp;

    int m = min(__ldg(cnt + node), CAP);
    float di = rsqrtf(1.0f + (float)__ldg(cnt + node));
    float w = di * di;

    size_t beg = (size_t)node << CAPSHIFT;
    size_t end = beg + m;

    const float2* lin2 = (const float2*)lin;
    float2 v = __ldg(lin2 + (size_t)node * 32 + lane);
    float2 b = __ldg(((const float2*)bias) + lane);
    float ax = fmaf(w, v.x, b.x);
    float ay = fmaf(w, v.y, b.y);

    size_t i = beg;
    for (; i + 2 <= end; i += 2) {
        uint2 e0 = __ldg(csr + i);
        uint2 e1 = __ldg(csr + i + 1);
        float2 s0 = __ldg(lin2 + (size_t)e0.x * 32 + lane);
        float2 s1 = __ldg(lin2 + (size_t)e1.x * 32 + lane);
        float w0 = __uint_as_float(e0.y);
        float w1 = __uint_as_float(e1.y);
        ax = fmaf(w0, s0.x, ax); ay = fmaf(w0, s0.y, ay);
        ax = fmaf(w1, s1.x, ax); ay = fmaf(w1, s1.y, ay);
    }
    if (i < end) {
        uint2 e0 = __ldg(csr + i);
        float2 s0 = __ldg(lin2 + (size_t)e0.x * 32 + lane);
        float w0 = __uint_as_float(e0.y);
        ax = fmaf(w0, s0.x, ax); ay = fmaf(w0, s0.y, ay);
    }

    float2 o;
    o.x = lrelu1(ax);
    o.y = lrelu1(ay);
    ((float2*)outp)[(size_t)node * 32 + lane] = o;
}

// ---------------- launch ----------------
extern "C" void kernel_launch(void* const* d_in, const int* in_sizes, int n_in,
                              void* d_out, int out_size) {
    const float*        x  = (const float*)d_in[0];
    const unsigned int* ei = (const unsigned int*)d_in[1];
    const float*        W1 = (const float*)d_in[2];
    const float*        b1 = (const float*)d_in[3];
    const float*        W2 = (const float*)d_in[4];
    const float*        b2 = (const float*)d_in[5];
    const float*        W3 = (const float*)d_in[6];
    const float*        b3 = (const float*)d_in[7];
    float* out = (float*)d_out;

    const int n = in_sizes[0] / HID;        // 100000
    const int E = in_sizes[1] / 2;          // 1600000

    float* bufA;  cudaGetSymbolAddress((void**)&bufA, g_bufA);
    float* bufB;  cudaGetSymbolAddress((void**)&bufB, g_bufB);
    int*   cnt;   cudaGetSymbolAddress((void**)&cnt,  g_cnt);
    uint2* csr;   cudaGetSymbolAddress((void**)&csr,  g_csr);

    const int T = 256;
    int gn  = (n + T - 1) / T;
    int gE  = (E + T - 1) / T;
    int gRow = (n + 127) / 128;              // row per thread
    int gWarp = (n * 32 + T - 1) / T;        // warp per node

    // build bucketed adjacency
    k_detect_zero<<<1 + gn, T>>>(ei, cnt, n);
    k_fill<<<gE, T>>>(ei, cnt, csr, E, n);
    k_norm<<<gWarp, T>>>(cnt, csr, n);

    // layer 1
    k_gemm64<<<gRow, 128>>>(x, W1, bufA, n);
    k_gather<<<gWarp, T>>>(bufA, csr, cnt, b1, bufB, n);
    // layer 2
    k_gemm64<<<gRow, 128>>>(bufB, W2, bufA, n);
    k_gather<<<gWarp, T>>>(bufA, csr, cnt, b2, bufB, n);
    // layer 3 -> d_out directly (plain stores only)
    k_gemm64<<<gRow, 128>>>(bufB, W3, bufA, n);
    k_gather<<<gWarp, T>>>(bufA, csr, cnt, b3, out, n);
}

// round 10
// speedup vs baseline: 1.0570x; 1.0570x over previous
#include <cuda_runtime.h>
#include <stdint.h>

#define N_NODES 100000
#define E_EDGES 1600000
#define HID 64
#define SCAN_B 512

// ---------------- scratch (no allocation allowed) ----------------
__device__ float g_bufA[N_NODES * HID];        // h_lin (GEMM out)
__device__ float g_bufB[N_NODES * HID];        // layer output h
__device__ float g_dinv[N_NODES];
__device__ int   g_cnt[N_NODES];               // per-dst edge counts
__device__ int   g_off[N_NODES + 1];           // CSR offsets
__device__ int   g_cur[N_NODES];               // fill cursors (init from off)
__device__ int   g_bsum[(N_NODES + SCAN_B - 1) / SCAN_B];
__device__ uint2 g_csr[E_EDGES];               // {src, norm_bits} sorted by dst
__device__ int   g_is64;                       // 1 if edge_index is int64

__device__ __forceinline__ float lrelu1(float v) {
    return fmaxf(v, 0.f) + 0.01f * fminf(v, 0.f);
}

// ---------------- dtype detection ----------
__global__ void k_detect(const unsigned int* __restrict__ u32buf) {
    __shared__ unsigned int s_or[256];
    unsigned int acc = 0;
    for (int i = threadIdx.x; i < 2048; i += 256)
        acc |= u32buf[2 * i + 1];          // hi word of candidate int64 #i
    s_or[threadIdx.x] = acc;
    __syncthreads();
    for (int s = 128; s > 0; s >>= 1) {
        if (threadIdx.x < s) s_or[threadIdx.x] |= s_or[threadIdx.x + s];
        __syncthreads();
    }
    if (threadIdx.x == 0) g_is64 = (s_or[0] == 0) ? 1 : 0;
}

__device__ __forceinline__ int load_idx(const unsigned int* u32buf, long long elem, int is64, int n) {
    unsigned int v = is64 ? u32buf[2 * elem] : u32buf[elem];
    int iv = (int)v;
    return min(max(iv, 0), n - 1);
}

// ---------------- graph precompute ----------------
__global__ void k_zero(int* __restrict__ cnt, int n) {
    int i = blockIdx.x * blockDim.x + threadIdx.x;
    if (i < n) cnt[i] = 0;
}

__global__ void k_count(const unsigned int* __restrict__ ei, int* __restrict__ cnt,
                        int E, int n) {
    int e = blockIdx.x * blockDim.x + threadIdx.x;
    if (e < E) {
        int is64 = g_is64;
        int d = load_idx(ei, (long long)E + e, is64, n);
        atomicAdd(cnt + d, 1);
    }
}

// ---------------- scan over cnt -> off, fused dinv ----------------
__global__ void k_scan_block(const int* __restrict__ cnt, int* __restrict__ off,
                             int* __restrict__ bsum, float* __restrict__ dinv, int n) {
    __shared__ int s[SCAN_B];
    int i = blockIdx.x * SCAN_B + threadIdx.x;
    int v = (i < n) ? cnt[i] : 0;
    if (i < n) dinv[i] = rsqrtf(1.0f + (float)v);       // +1 self loop (fused)
    s[threadIdx.x] = v;
    __syncthreads();
#pragma unroll
    for (int d = 1; d < SCAN_B; d <<= 1) {
        int t = (threadIdx.x >= d) ? s[threadIdx.x - d] : 0;
        __syncthreads();
        s[threadIdx.x] += t;
        __syncthreads();
    }
    if (i < n) off[i] = s[threadIdx.x] - v;             // exclusive within block
    if (threadIdx.x == SCAN_B - 1) bsum[blockIdx.x] = s[SCAN_B - 1];
}

__global__ void k_scan_bsum(int* __restrict__ bsum, int nb) {   // nb <= SCAN_B
    __shared__ int s[SCAN_B];
    int v = (threadIdx.x < nb) ? bsum[threadIdx.x] : 0;
    s[threadIdx.x] = v;
    __syncthreads();
#pragma unroll
    for (int d = 1; d < SCAN_B; d <<= 1) {
        int t = (threadIdx.x >= d) ? s[threadIdx.x - d] : 0;
        __syncthreads();
        s[threadIdx.x] += t;
        __syncthreads();
    }
    if (threadIdx.x < nb) bsum[threadIdx.x] = s[threadIdx.x] - v;   // exclusive
}

__global__ void k_scan_add(int* __restrict__ off, int* __restrict__ cur,
                           const int* __restrict__ bsum, int n, int E) {
    int i = blockIdx.x * blockDim.x + threadIdx.x;
    if (i < n) {
        int o = off[i] + bsum[i / SCAN_B];
        off[i] = o;
        cur[i] = o;
    }
    if (i == 0) off[n] = E;
}

// ---------------- CSR fill ----------------
__global__ void k_fill(const unsigned int* __restrict__ ei, const float* __restrict__ dinv,
                       int* __restrict__ cur, uint2* __restrict__ csr, int E, int n) {
    int e = blockIdx.x * blockDim.x + threadIdx.x;
    if (e < E) {
        int is64 = g_is64;
        int s = load_idx(ei, e, is64, n);
        int d = load_idx(ei, (long long)E + e, is64, n);
        float nw = dinv[s] * dinv[d];
        int pos = atomicAdd(cur + d, 1);
        csr[pos] = make_uint2((unsigned int)s, __float_as_uint(nw));
    }
}

// ---------------- GEMM: out[n,64] = in[n,64] @ W[64,64] --------------------
// Register-blocked: each thread computes 4 rows x 16 cols. The col-quarter is
// warp-uniform (q = warp & 3) so all smem W reads are broadcast (no conflicts)
// and reused across 4 rows -> 4x less LDS traffic than row-per-thread.
__global__ __launch_bounds__(256)
void k_gemm64(const float* __restrict__ in, const float* __restrict__ W,
              float* __restrict__ out, int n) {
    __shared__ float Ws[64 * 64];
    for (int i = threadIdx.x; i < 64 * 16; i += 256)
        ((float4*)Ws)[i] = ((const float4*)W)[i];
    __syncthreads();

    int warp = threadIdx.x >> 5;      // 0..7
    int lane = threadIdx.x & 31;
    int q    = warp & 3;              // col quarter: cols [16q, 16q+16)
    int tile = warp >> 2;             // 0..1: 128-row tile within block
    int rowbase = blockIdx.x * 256 + tile * 128 + lane;   // rows rowbase + 32*j

    float acc[4][16];
#pragma unroll
    for (int j = 0; j < 4; j++)
#pragma unroll
        for (int c = 0; c < 16; c++) acc[j][c] = 0.f;

    bool valid[4];
    const float4* inp[4];
#pragma unroll
    for (int j = 0; j < 4; j++) {
        int r = rowbase + 32 * j;
        valid[j] = (r < n);
        inp[j] = (const float4*)(in + (size_t)(valid[j] ? r : 0) * HID);
    }

    for (int k4 = 0; k4 < 16; k4++) {
        float4 a[4];
#pragma unroll
        for (int j = 0; j < 4; j++) a[j] = inp[j][k4];

#pragma unroll
        for (int kk = 0; kk < 4; kk++) {
            const float4* wq = (const float4*)(Ws + (k4 * 4 + kk) * 64 + q * 16);
            float4 w0 = wq[0], w1 = wq[1], w2 = wq[2], w3 = wq[3];
            float wv[16] = {w0.x, w0.y, w0.z, w0.w, w1.x, w1.y, w1.z, w1.w,
                            w2.x, w2.y, w2.z, w2.w, w3.x, w3.y, w3.z, w3.w};
#pragma unroll
            for (int j = 0; j < 4; j++) {
                float av = (kk == 0) ? a[j].x : (kk == 1) ? a[j].y
                         : (kk == 2) ? a[j].z : a[j].w;
#pragma unroll
                for (int c = 0; c < 16; c++)
                    acc[j][c] = fmaf(av, wv[c], acc[j][c]);
            }
        }
    }

#pragma unroll
    for (int j = 0; j < 4; j++) {
        int r = rowbase + 32 * j;
        if (valid[j]) {
            float4* outr = (float4*)(out + (size_t)r * HID + q * 16);
#pragma unroll
            for (int c4 = 0; c4 < 4; c4++)
                outr[c4] = make_float4(acc[j][4 * c4], acc[j][4 * c4 + 1],
                                       acc[j][4 * c4 + 2], acc[j][4 * c4 + 3]);
        }
    }
}

// ---------------- CSR gather (exact R8 body) ----------------
__global__ __launch_bounds__(256)
void k_gather(const float* __restrict__ lin, const uint2* __restrict__ csr,
              const int* __restrict__ off, const float* __restrict__ dinv,
              const float* __restrict__ bias, float* __restrict__ outp, int n) {
    int warp = (blockIdx.x * blockDim.x + threadIdx.x) >> 5;
    int lane = threadIdx.x & 31;
    if (warp >= n) return;
    int node = warp;

    int beg = __ldg(off + node);
    int end = __ldg(off + node + 1);
    float di = __ldg(dinv + node);
    float w = di * di;

    const float2* lin2 = (const float2*)lin;
    float2 v = __ldg(lin2 + (size_t)node * 32 + lane);
    float2 b = __ldg(((const float2*)bias) + lane);
    float ax = fmaf(w, v.x, b.x);
    float ay = fmaf(w, v.y, b.y);

    int i = beg;
    for (; i + 2 <= end; i += 2) {
        uint2 e0 = __ldg(csr + i);
        uint2 e1 = __ldg(csr + i + 1);
        float2 s0 = __ldg(lin2 + (size_t)e0.x * 32 + lane);
        float2 s1 = __ldg(lin2 + (size_t)e1.x * 32 + lane);
        float w0 = __uint_as_float(e0.y);
        float w1 = __uint_as_float(e1.y);
        ax = fmaf(w0, s0.x, ax); ay = fmaf(w0, s0.y, ay);
        ax = fmaf(w1, s1.x, ax); ay = fmaf(w1, s1.y, ay);
    }
    if (i < end) {
        uint2 e0 = __ldg(csr + i);
        float2 s0 = __ldg(lin2 + (size_t)e0.x * 32 + lane);
        float w0 = __uint_as_float(e0.y);
        ax = fmaf(w0, s0.x, ax); ay = fmaf(w0, s0.y, ay);
    }

    float2 o;
    o.x = lrelu1(ax);
    o.y = lrelu1(ay);
    ((float2*)outp)[(size_t)node * 32 + lane] = o;
}

// ---------------- launch ----------------
extern "C" void kernel_launch(void* const* d_in, const int* in_sizes, int n_in,
                              void* d_out, int out_size) {
    const float*        x  = (const float*)d_in[0];
    const unsigned int* ei = (const unsigned int*)d_in[1];
    const float*        W1 = (const float*)d_in[2];
    const float*        b1 = (const float*)d_in[3];
    const float*        W2 = (const float*)d_in[4];
    const float*        b2 = (const float*)d_in[5];
    const float*        W3 = (const float*)d_in[6];
    const float*        b3 = (const float*)d_in[7];
    float* out = (float*)d_out;

    const int n = in_sizes[0] / HID;        // 100000
    const int E = in_sizes[1] / 2;          // 1600000

    float* bufA;  cudaGetSymbolAddress((void**)&bufA, g_bufA);
    float* bufB;  cudaGetSymbolAddress((void**)&bufB, g_bufB);
    float* dinv;  cudaGetSymbolAddress((void**)&dinv, g_dinv);
    int*   cnt;   cudaGetSymbolAddress((void**)&cnt,  g_cnt);
    int*   off;   cudaGetSymbolAddress((void**)&off,  g_off);
    int*   cur;   cudaGetSymbolAddress((void**)&cur,  g_cur);
    int*   bsum;  cudaGetSymbolAddress((void**)&bsum, g_bsum);
    uint2* csr;   cudaGetSymbolAddress((void**)&csr,  g_csr);

    const int T = 256;
    int gn  = (n + T - 1) / T;
    int gE  = (E + T - 1) / T;
    int nb  = (n + SCAN_B - 1) / SCAN_B;     // 196
    int gGem = (n + 255) / 256;              // 256 rows per block
    int gGat = (n * 32 + T - 1) / T;         // warp per node

    // dtype detection + CSR build
    k_detect<<<1, 256>>>(ei);
    k_zero<<<gn, T>>>(cnt, n);
    k_count<<<gE, T>>>(ei, cnt, E, n);
    k_scan_block<<<nb, SCAN_B>>>(cnt, off, bsum, dinv, n);
    k_scan_bsum<<<1, SCAN_B>>>(bsum, nb);
    k_scan_add<<<gn, T>>>(off, cur, bsum, n, E);
    k_fill<<<gE, T>>>(ei, dinv, cur, csr, E, n);

    // layer 1
    k_gemm64<<<gGem, T>>>(x, W1, bufA, n);
    k_gather<<<gGat, T>>>(bufA, csr, off, dinv, b1, bufB, n);
    // layer 2
    k_gemm64<<<gGem, T>>>(bufB, W2, bufA, n);
    k_gather<<<gGat, T>>>(bufA, csr, off, dinv, b2, bufB, n);
    // layer 3 -> d_out directly (plain stores only)
    k_gemm64<<<gGem, T>>>(bufB, W3, bufA, n);
    k_gather<<<gGat, T>>>(bufA, csr, off, dinv, b3, out, n);
}

// round 11
// speedup vs baseline: 1.1947x; 1.1304x over previous
#include <cuda_runtime.h>
#include <stdint.h>

#define N_NODES 100000
#define E_EDGES 1600000
#define HID 64
#define SCAN_B 512

// ---------------- scratch (no allocation allowed) ----------------
__device__ float g_bufA[N_NODES * HID];        // dinv-scaled GEMM out
__device__ float g_bufB[N_NODES * HID];        // layer output h
__device__ float g_dinv[N_NODES];
__device__ int   g_cnt[N_NODES];               // per-dst edge counts
__device__ int   g_off[N_NODES + 1];           // CSR offsets
__device__ int   g_cur[N_NODES];               // fill cursors (init from off)
__device__ int   g_bsum[(N_NODES + SCAN_B - 1) / SCAN_B];
__device__ int   g_csr[E_EDGES];               // src indices sorted by dst
__device__ int   g_is64;                       // 1 if edge_index is int64

__device__ __forceinline__ float lrelu1(float v) {
    return fmaxf(v, 0.f) + 0.01f * fminf(v, 0.f);
}

// ---------------- dtype detection ----------
__global__ void k_detect(const unsigned int* __restrict__ u32buf) {
    __shared__ unsigned int s_or[256];
    unsigned int acc = 0;
    for (int i = threadIdx.x; i < 2048; i += 256)
        acc |= u32buf[2 * i + 1];          // hi word of candidate int64 #i
    s_or[threadIdx.x] = acc;
    __syncthreads();
    for (int s = 128; s > 0; s >>= 1) {
        if (threadIdx.x < s) s_or[threadIdx.x] |= s_or[threadIdx.x + s];
        __syncthreads();
    }
    if (threadIdx.x == 0) g_is64 = (s_or[0] == 0) ? 1 : 0;
}

__device__ __forceinline__ int load_idx(const unsigned int* u32buf, long long elem, int is64, int n) {
    unsigned int v = is64 ? u32buf[2 * elem] : u32buf[elem];
    int iv = (int)v;
    return min(max(iv, 0), n - 1);
}

// ---------------- graph precompute ----------------
__global__ void k_zero(int* __restrict__ cnt, int n) {
    int i = blockIdx.x * blockDim.x + threadIdx.x;
    if (i < n) cnt[i] = 0;
}

__global__ void k_count(const unsigned int* __restrict__ ei, int* __restrict__ cnt,
                        int E, int n) {
    int e = blockIdx.x * blockDim.x + threadIdx.x;
    if (e < E) {
        int is64 = g_is64;
        int d = load_idx(ei, (long long)E + e, is64, n);
        atomicAdd(cnt + d, 1);
    }
}

// ---------------- scan over cnt -> off, fused dinv ----------------
__global__ void k_scan_block(const int* __restrict__ cnt, int* __restrict__ off,
                             int* __restrict__ bsum, float* __restrict__ dinv, int n) {
    __shared__ int s[SCAN_B];
    int i = blockIdx.x * SCAN_B + threadIdx.x;
    int v = (i < n) ? cnt[i] : 0;
    if (i < n) dinv[i] = rsqrtf(1.0f + (float)v);       // +1 self loop (fused)
    s[threadIdx.x] = v;
    __syncthreads();
#pragma unroll
    for (int d = 1; d < SCAN_B; d <<= 1) {
        int t = (threadIdx.x >= d) ? s[threadIdx.x - d] : 0;
        __syncthreads();
        s[threadIdx.x] += t;
        __syncthreads();
    }
    if (i < n) off[i] = s[threadIdx.x] - v;             // exclusive within block
    if (threadIdx.x == SCAN_B - 1) bsum[blockIdx.x] = s[SCAN_B - 1];
}

__global__ void k_scan_bsum(int* __restrict__ bsum, int nb) {   // nb <= SCAN_B
    __shared__ int s[SCAN_B];
    int v = (threadIdx.x < nb) ? bsum[threadIdx.x] : 0;
    s[threadIdx.x] = v;
    __syncthreads();
#pragma unroll
    for (int d = 1; d < SCAN_B; d <<= 1) {
        int t = (threadIdx.x >= d) ? s[threadIdx.x - d] : 0;
        __syncthreads();
        s[threadIdx.x] += t;
        __syncthreads();
    }
    if (threadIdx.x < nb) bsum[threadIdx.x] = s[threadIdx.x] - v;   // exclusive
}

__global__ void k_scan_add(int* __restrict__ off, int* __restrict__ cur,
                           const int* __restrict__ bsum, int n, int E) {
    int i = blockIdx.x * blockDim.x + threadIdx.x;
    if (i < n) {
        int o = off[i] + bsum[i / SCAN_B];
        off[i] = o;
        cur[i] = o;
    }
    if (i == 0) off[n] = E;
}

// ---------------- CSR fill (src index only; no norms) ----------------
__global__ void k_fill(const unsigned int* __restrict__ ei,
                       int* __restrict__ cur, int* __restrict__ csr, int E, int n) {
    int e = blockIdx.x * blockDim.x + threadIdx.x;
    if (e < E) {
        int is64 = g_is64;
        int s = load_idx(ei, e, is64, n);
        int d = load_idx(ei, (long long)E + e, is64, n);
        int pos = atomicAdd(cur + d, 1);
        csr[pos] = s;
    }
}

// ---------------- GEMM: out[n,64] = dinv[row] * (in[n,64] @ W[64,64]) ------
// (R8 row-per-thread body + dinv epilogue scale)
__global__ __launch_bounds__(128)
void k_gemm64(const float* __restrict__ in, const float* __restrict__ W,
              const float* __restrict__ dinvv, float* __restrict__ out, int n) {
    __shared__ float Ws[64 * 64];
    for (int i = threadIdx.x; i < 64 * 16; i += blockDim.x)
        ((float4*)Ws)[i] = ((const float4*)W)[i];
    __syncthreads();

    int row = blockIdx.x * blockDim.x + threadIdx.x;
    if (row >= n) return;

    float acc[64];
#pragma unroll
    for (int j = 0; j < 64; j++) acc[j] = 0.f;

    const float4* inr = (const float4*)(in + (size_t)row * HID);

#pragma unroll 4
    for (int k4 = 0; k4 < 16; k4++) {
        float4 v = inr[k4];
        float av[4] = {v.x, v.y, v.z, v.w};
#pragma unroll
        for (int kk = 0; kk < 4; kk++) {
            const float* wrow = Ws + (k4 * 4 + kk) * 64;
#pragma unroll
            for (int j = 0; j < 64; j++)
                acc[j] = fmaf(av[kk], wrow[j], acc[j]);
        }
    }

    float di = __ldg(dinvv + row);
    float4* outr = (float4*)(out + (size_t)row * HID);
#pragma unroll
    for (int j = 0; j < 16; j++)
        outr[j] = make_float4(di * acc[4 * j], di * acc[4 * j + 1],
                              di * acc[4 * j + 2], di * acc[4 * j + 3]);
}

// ---------------- gather: h[node] = lrelu(dinv[node]*(bufA[node]
//                                    + sum_e bufA[src_e]) + bias) ----------
// One warp per destination node; lane owns 2 feature columns (float2).
__global__ __launch_bounds__(256)
void k_gather(const float* __restrict__ lin, const int* __restrict__ csr,
              const int* __restrict__ off, const float* __restrict__ dinv,
              const float* __restrict__ bias, float* __restrict__ outp, int n) {
    int warp = (blockIdx.x * blockDim.x + threadIdx.x) >> 5;
    int lane = threadIdx.x & 31;
    if (warp >= n) return;
    int node = warp;

    int beg = __ldg(off + node);
    int end = __ldg(off + node + 1);

    const float2* lin2 = (const float2*)lin;
    float2 t = __ldg(lin2 + (size_t)node * 32 + lane);   // self term (pre-scaled)
    float tx = t.x, ty = t.y;

    int i = beg;
    for (; i + 2 <= end; i += 2) {
        int s0 = __ldg(csr + i);
        int s1 = __ldg(csr + i + 1);
        float2 v0 = __ldg(lin2 + (size_t)s0 * 32 + lane);
        float2 v1 = __ldg(lin2 + (size_t)s1 * 32 + lane);
        tx += v0.x; ty += v0.y;
        tx += v1.x; ty += v1.y;
    }
    if (i < end) {
        int s0 = __ldg(csr + i);
        float2 v0 = __ldg(lin2 + (size_t)s0 * 32 + lane);
        tx += v0.x; ty += v0.y;
    }

    float di = __ldg(dinv + node);
    float2 b = __ldg(((const float2*)bias) + lane);
    float2 o;
    o.x = lrelu1(fmaf(di, tx, b.x));
    o.y = lrelu1(fmaf(di, ty, b.y));
    ((float2*)outp)[(size_t)node * 32 + lane] = o;
}

// ---------------- launch ----------------
extern "C" void kernel_launch(void* const* d_in, const int* in_sizes, int n_in,
                              void* d_out, int out_size) {
    const float*        x  = (const float*)d_in[0];
    const unsigned int* ei = (const unsigned int*)d_in[1];
    const float*        W1 = (const float*)d_in[2];
    const float*        b1 = (const float*)d_in[3];
    const float*        W2 = (const float*)d_in[4];
    const float*        b2 = (const float*)d_in[5];
    const float*        W3 = (const float*)d_in[6];
    const float*        b3 = (const float*)d_in[7];
    float* out = (float*)d_out;

    const int n = in_sizes[0] / HID;        // 100000
    const int E = in_sizes[1] / 2;          // 1600000

    float* bufA;  cudaGetSymbolAddress((void**)&bufA, g_bufA);
    float* bufB;  cudaGetSymbolAddress((void**)&bufB, g_bufB);
    float* dinv;  cudaGetSymbolAddress((void**)&dinv, g_dinv);
    int*   cnt;   cudaGetSymbolAddress((void**)&cnt,  g_cnt);
    int*   off;   cudaGetSymbolAddress((void**)&off,  g_off);
    int*   cur;   cudaGetSymbolAddress((void**)&cur,  g_cur);
    int*   bsum;  cudaGetSymbolAddress((void**)&bsum, g_bsum);
    int*   csr;   cudaGetSymbolAddress((void**)&csr,  g_csr);

    const int T = 256;
    int gn  = (n + T - 1) / T;
    int gE  = (E + T - 1) / T;
    int nb  = (n + SCAN_B - 1) / SCAN_B;     // 196
    int gRow = (n + 127) / 128;              // row per thread
    int gGat = (n * 32 + T - 1) / T;         // warp per node

    // dtype detection + CSR build
    k_detect<<<1, 256>>>(ei);
    k_zero<<<gn, T>>>(cnt, n);
    k_count<<<gE, T>>>(ei, cnt, E, n);
    k_scan_block<<<nb, SCAN_B>>>(cnt, off, bsum, dinv, n);
    k_scan_bsum<<<1, SCAN_B>>>(bsum, nb);
    k_scan_add<<<gn, T>>>(off, cur, bsum, n, E);
    k_fill<<<gE, T>>>(ei, cur, csr, E, n);

    // layer 1
    k_gemm64<<<gRow, 128>>>(x, W1, dinv, bufA, n);
    k_gather<<<gGat, T>>>(bufA, csr, off, dinv, b1, bufB, n);
    // layer 2
    k_gemm64<<<gRow, 128>>>(bufB, W2, dinv, bufA, n);
    k_gather<<<gGat, T>>>(bufA, csr, off, dinv, b2, bufB, n);
    // layer 3 -> d_out directly (plain stores only)
    k_gemm64<<<gRow, 128>>>(bufB, W3, dinv, bufA, n);
    k_gather<<<gGat, T>>>(bufA, csr, off, dinv, b3, out, n);
}